// round 15
// baseline (speedup 1.0000x reference)
#include <cuda_runtime.h>
#include <math.h>

// Problem geometry
#define H_IN   384
#define W_IN   512
#define H_OUT  374
#define W_OUT  502
#define NCH    48
#define TOTAL_OUT 9011904.0  // 48 * 374 * 502

// Tiling — 4 CTAs/SM (smem 55296 B, 64-reg target)  [R12 geometry]
#define TX 64
#define TY 44
#define IN_TY 54     // TY + 10
#define TILES_X 8
#define TILES_Y 9    // ceil(374/44)
#define RPT 11       // output rows per thread in vertical phase (4*11 = 44 = TY)
#define NBLOCKS (TILES_X * TILES_Y * NCH)   // 3456

// Gaussian weights (win=11, sigma=1.5) as literals -> imm-form FFMA (rt_SMSP=1)
#define GW0 0.00102838f
#define GW1 0.00759874f
#define GW2 0.03600077f
#define GW3 0.10936073f
#define GW4 0.21300553f
#define GW5 0.26601171f

__device__ double g_sum = 0.0;
__device__ unsigned int g_done = 0u;

__global__ __launch_bounds__(256, 4)
void ssim_kernel(const float* __restrict__ X, const float* __restrict__ Y,
                 float* __restrict__ out, int out_n) {
    constexpr float W[11] = {GW0, GW1, GW2, GW3, GW4, GW5, GW4, GW3, GW2, GW1, GW0};

    // smem (55296 B -> 4 CTAs/SM): single merged array
    //   hB[r*TX+c] = {mu1, mu2, A=E[x^2+y^2], B=E[xy]}
    // vertical phase reads one LDS.128 per row instead of 2x LDS.64.
    extern __shared__ float4 hB[];

    const int tid = threadIdx.x;
    const int tx0 = blockIdx.x * TX;
    const int ty0 = blockIdx.y * TY;
    const size_t chOff = (size_t)blockIdx.z * (H_IN * W_IN);
    const float* Xc = X + chOff;
    const float* Yc = Y + chOff;

    // ---- horizontal blur straight from gmem; scalar imm-form FFMA only.
    // 54 rows x 16 groups of 4 output cols; window = 14 elems = 4 float4s.
    for (int i = tid; i < IN_TY * 16; i += 256) {
        int r = i >> 4;
        int c0 = (i & 15) * 4;
        int gr = ty0 + r;
        bool rok = (gr < H_IN);
        const float* rx = Xc + gr * W_IN + tx0 + c0;
        const float* ry = Yc + gr * W_IN + tx0 + c0;

        float vx[16], vy[16];
#pragma unroll
        for (int q = 0; q < 4; ++q) {
            int gc = tx0 + c0 + 4 * q;           // multiple of 4, never straddles 512
            float4 a = make_float4(0.f, 0.f, 0.f, 0.f);
            float4 b = make_float4(0.f, 0.f, 0.f, 0.f);
            if (rok && gc < W_IN) {
                a = reinterpret_cast<const float4*>(rx)[q];
                b = reinterpret_cast<const float4*>(ry)[q];
            }
            vx[4*q+0] = a.x; vx[4*q+1] = a.y; vx[4*q+2] = a.z; vx[4*q+3] = a.w;
            vy[4*q+0] = b.x; vy[4*q+1] = b.y; vy[4*q+2] = b.z; vy[4*q+3] = b.w;
        }

        int base = r * TX + c0;

        // pass 1: mu taps; store {mu1,mu2} halves now (STS.64) to release regs
        {
            float m1[4] = {0,0,0,0}, m2[4] = {0,0,0,0};
#pragma unroll
            for (int k = 0; k < 11; ++k) {
#pragma unroll
                for (int o = 0; o < 4; ++o) {
                    m1[o] = fmaf(W[k], vx[k + o], m1[o]);
                    m2[o] = fmaf(W[k], vy[k + o], m2[o]);
                }
            }
#pragma unroll
            for (int o = 0; o < 4; ++o)
                reinterpret_cast<float2*>(&hB[base + o])[0] = make_float2(m1[o], m2[o]);
        }

        // in-place transform: vx <- x^2 + y^2, vy <- x*y
#pragma unroll
        for (int j = 0; j < 14; ++j) {
            float a = vx[j], b = vy[j];
            vx[j] = fmaf(a, a, b * b);
            vy[j] = a * b;
        }

        // pass 2: A/B taps; store {A,B} halves (STS.64 at +8)
        {
            float sA[4] = {0,0,0,0}, sB[4] = {0,0,0,0};
#pragma unroll
            for (int k = 0; k < 11; ++k) {
#pragma unroll
                for (int o = 0; o < 4; ++o) {
                    sA[o] = fmaf(W[k], vx[k + o], sA[o]);
                    sB[o] = fmaf(W[k], vy[k + o], sB[o]);
                }
            }
#pragma unroll
            for (int o = 0; o < 4; ++o)
                reinterpret_cast<float2*>(&hB[base + o])[1] = make_float2(sA[o], sB[o]);
        }
    }
    __syncthreads();

    // ---- vertical blur + ssim map: 4 strips of 11 rows, 64 cols.
    // One LDS.128 per input row -> all four fields.
    float local = 0.f;
    {
        int c  = tid & 63;
        int r0 = (tid >> 6) * RPT;

        float a0[RPT], a1[RPT], a2[RPT], a3[RPT];
#pragma unroll
        for (int o = 0; o < RPT; ++o) { a0[o] = a1[o] = a2[o] = a3[o] = 0.f; }

#pragma unroll
        for (int k = 0; k < RPT + 10; ++k) {      // 21 input rows
            float4 v = hB[(r0 + k) * TX + c];     // LDS.128 {mu1, mu2, A, B}
#pragma unroll
            for (int o = 0; o < RPT; ++o) {
                int t = k - o;
                if (t >= 0 && t < 11) {
                    a0[o] = fmaf(W[t], v.x, a0[o]);
                    a1[o] = fmaf(W[t], v.y, a1[o]);
                    a2[o] = fmaf(W[t], v.z, a2[o]);
                    a3[o] = fmaf(W[t], v.w, a3[o]);
                }
            }
        }

        int gc = tx0 + c;
        const float C1 = 1e-4f, C2 = 9e-4f;
#pragma unroll
        for (int o = 0; o < RPT; ++o) {
            int gr = ty0 + r0 + o;
            if (gr < H_OUT && gc < W_OUT) {
                float mu1 = a0[o], mu2 = a1[o];
                float mu1s = mu1 * mu1;
                float mu2s = mu2 * mu2;
                float m12  = mu1 * mu2;
                float sSum = a2[o] - mu1s - mu2s;   // sigma1^2 + sigma2^2
                float s12  = a3[o] - m12;
                float num = (2.f * m12 + C1) * (2.f * s12 + C2);
                float den = (mu1s + mu2s + C1) * (sSum + C2);
                local += __fdividef(num, den);
            }
        }
    }

    // ---- block reduction + one double atomic per CTA; last CTA finalizes
#pragma unroll
    for (int off = 16; off; off >>= 1)
        local += __shfl_xor_sync(0xffffffffu, local, off);

    __shared__ float red[8];
    int lane = tid & 31, wid = tid >> 5;
    if (lane == 0) red[wid] = local;
    __syncthreads();
    if (tid == 0) {
        float s = 0.f;
#pragma unroll
        for (int i2 = 0; i2 < 8; ++i2) s += red[i2];
        atomicAdd(&g_sum, (double)s);
        __threadfence();
        unsigned int old = atomicAdd(&g_done, 1u);
        if (old == NBLOCKS - 1u) {
            double t = *((volatile double*)&g_sum);
            float v = (float)(1.0 - t / TOTAL_OUT);
            for (int i2 = 0; i2 < out_n; ++i2) out[i2] = v;
            // reset for next graph replay (deterministic)
            g_sum = 0.0;
            g_done = 0u;
        }
    }
}

extern "C" void kernel_launch(void* const* d_in, const int* in_sizes, int n_in,
                              void* d_out, int out_size) {
    const float* pred   = (const float*)d_in[0];
    const float* target = (const float*)d_in[1];

    constexpr size_t SMEM = (size_t)(IN_TY * TX) * sizeof(float4);   // 55296 B
    cudaFuncSetAttribute(ssim_kernel, cudaFuncAttributeMaxDynamicSharedMemorySize, (int)SMEM);

    dim3 grid(TILES_X, TILES_Y, NCH);
    ssim_kernel<<<grid, 256, SMEM>>>(pred, target, (float*)d_out, out_size);
}

// round 17
// speedup vs baseline: 1.0959x; 1.0959x over previous
#include <cuda_runtime.h>
#include <math.h>

// Problem geometry
#define H_IN   384
#define W_IN   512
#define H_OUT  374
#define W_OUT  502
#define NCH    48
#define TOTAL_OUT 9011904.0  // 48 * 374 * 502

// Tiling — 4 CTAs/SM; IN_TY*16 = 768 = 3 items/thread exactly (no h-phase skew)
#define TX 64
#define TY 38
#define IN_TY 48     // TY + 10
#define TILES_X 8
#define TILES_Y 10   // 380 rows; 374..379 masked
#define RPT 10       // 4 strips x 10 = 40 >= TY; tail masked
#define NBLOCKS (TILES_X * TILES_Y * NCH)   // 3840

// Gaussian weights (win=11, sigma=1.5) as literals -> imm-form FFMA (rt_SMSP=1)
#define GW0 0.00102838f
#define GW1 0.00759874f
#define GW2 0.03600077f
#define GW3 0.10936073f
#define GW4 0.21300553f
#define GW5 0.26601171f

__device__ double g_sum = 0.0;
__device__ unsigned int g_done = 0u;

__global__ __launch_bounds__(256, 4)
void ssim_kernel(const float* __restrict__ X, const float* __restrict__ Y,
                 float* __restrict__ out, int out_n) {
    constexpr float W[11] = {GW0, GW1, GW2, GW3, GW4, GW5, GW4, GW3, GW2, GW1, GW0};

    // smem (49152 B -> 4 CTAs/SM), R12-proven split interleaved layout:
    //   hBa: float2[IN_TY*TX]  {mu1, mu2}
    //   hBb: float2[IN_TY*TX]  {A=E[x^2+y^2], B=E[xy]}
    extern __shared__ float smem[];
    float2* hBa = reinterpret_cast<float2*>(smem);
    float2* hBb = hBa + IN_TY * TX;

    const int tid = threadIdx.x;
    const int tx0 = blockIdx.x * TX;
    const int ty0 = blockIdx.y * TY;
    const size_t chOff = (size_t)blockIdx.z * (H_IN * W_IN);
    const float* Xc = X + chOff;
    const float* Yc = Y + chOff;

    // ---- horizontal blur straight from gmem; scalar imm-form FFMA only.
    // 48 rows x 16 groups of 4 output cols = 768 items = exactly 3 per thread.
    for (int i = tid; i < IN_TY * 16; i += 256) {
        int r = i >> 4;
        int c0 = (i & 15) * 4;
        int gr = ty0 + r;
        bool rok = (gr < H_IN);
        const float* rx = Xc + gr * W_IN + tx0 + c0;
        const float* ry = Yc + gr * W_IN + tx0 + c0;

        float vx[16], vy[16];
#pragma unroll
        for (int q = 0; q < 4; ++q) {
            int gc = tx0 + c0 + 4 * q;           // multiple of 4, never straddles 512
            float4 a = make_float4(0.f, 0.f, 0.f, 0.f);
            float4 b = make_float4(0.f, 0.f, 0.f, 0.f);
            if (rok && gc < W_IN) {
                a = reinterpret_cast<const float4*>(rx)[q];
                b = reinterpret_cast<const float4*>(ry)[q];
            }
            vx[4*q+0] = a.x; vx[4*q+1] = a.y; vx[4*q+2] = a.z; vx[4*q+3] = a.w;
            vy[4*q+0] = b.x; vy[4*q+1] = b.y; vy[4*q+2] = b.z; vy[4*q+3] = b.w;
        }

        // pass 1: mu taps on raw values
        float m1[4] = {0,0,0,0}, m2[4] = {0,0,0,0};
#pragma unroll
        for (int k = 0; k < 11; ++k) {
#pragma unroll
            for (int o = 0; o < 4; ++o) {
                m1[o] = fmaf(W[k], vx[k + o], m1[o]);
                m2[o] = fmaf(W[k], vy[k + o], m2[o]);
            }
        }
        // store mu pair now (STS.128 pattern) to release regs before pass 2
        int base = r * TX + c0;
        reinterpret_cast<float4*>(hBa + base)[0] = make_float4(m1[0], m2[0], m1[1], m2[1]);
        reinterpret_cast<float4*>(hBa + base + 2)[0] = make_float4(m1[2], m2[2], m1[3], m2[3]);

        // in-place transform: vx <- x^2 + y^2, vy <- x*y
#pragma unroll
        for (int j = 0; j < 14; ++j) {
            float a = vx[j], b = vy[j];
            vx[j] = fmaf(a, a, b * b);
            vy[j] = a * b;
        }
        // pass 2: A/B taps on transformed values
        float sA[4] = {0,0,0,0}, sB[4] = {0,0,0,0};
#pragma unroll
        for (int k = 0; k < 11; ++k) {
#pragma unroll
            for (int o = 0; o < 4; ++o) {
                sA[o] = fmaf(W[k], vx[k + o], sA[o]);
                sB[o] = fmaf(W[k], vy[k + o], sB[o]);
            }
        }
        reinterpret_cast<float4*>(hBb + base)[0] = make_float4(sA[0], sB[0], sA[1], sB[1]);
        reinterpret_cast<float4*>(hBb + base + 2)[0] = make_float4(sA[2], sB[2], sA[3], sB[3]);
    }
    __syncthreads();

    // ---- vertical blur + ssim map: 4 strips of 10 rows (tail rows masked)
    float local = 0.f;
    {
        int c  = tid & 63;
        int r0 = (tid >> 6) * RPT;

        float a0[RPT], a1[RPT], a2[RPT], a3[RPT];
#pragma unroll
        for (int o = 0; o < RPT; ++o) { a0[o] = a1[o] = a2[o] = a3[o] = 0.f; }

#pragma unroll
        for (int k = 0; k < RPT + 10; ++k) {      // 20 input rows
            int rr = min(r0 + k, IN_TY - 1);      // clamp: strip 3 overrun guards (outputs masked)
            int off = rr * TX + c;
            float2 vm = hBa[off];                 // LDS.64 {mu1, mu2}
            float2 vp = hBb[off];                 // LDS.64 {A, B}
#pragma unroll
            for (int o = 0; o < RPT; ++o) {
                int t = k - o;
                if (t >= 0 && t < 11) {
                    a0[o] = fmaf(W[t], vm.x, a0[o]);
                    a1[o] = fmaf(W[t], vm.y, a1[o]);
                    a2[o] = fmaf(W[t], vp.x, a2[o]);
                    a3[o] = fmaf(W[t], vp.y, a3[o]);
                }
            }
        }

        int gc = tx0 + c;
        const float C1 = 1e-4f, C2 = 9e-4f;
#pragma unroll
        for (int o = 0; o < RPT; ++o) {
            int gr = ty0 + r0 + o;
            // r0+o < TY guards tile-tail rows (duplicates of next tile)
            if ((r0 + o < TY) && gr < H_OUT && gc < W_OUT) {
                float mu1 = a0[o], mu2 = a1[o];
                float mu1s = mu1 * mu1;
                float mu2s = mu2 * mu2;
                float m12  = mu1 * mu2;
                float sSum = a2[o] - mu1s - mu2s;   // sigma1^2 + sigma2^2
                float s12  = a3[o] - m12;
                float num = (2.f * m12 + C1) * (2.f * s12 + C2);
                float den = (mu1s + mu2s + C1) * (sSum + C2);
                local += __fdividef(num, den);
            }
        }
    }

    // ---- block reduction + one double atomic per CTA; last CTA finalizes
#pragma unroll
    for (int off = 16; off; off >>= 1)
        local += __shfl_xor_sync(0xffffffffu, local, off);

    __shared__ float red[8];
    int lane = tid & 31, wid = tid >> 5;
    if (lane == 0) red[wid] = local;
    __syncthreads();
    if (tid == 0) {
        float s = 0.f;
#pragma unroll
        for (int i2 = 0; i2 < 8; ++i2) s += red[i2];
        atomicAdd(&g_sum, (double)s);
        __threadfence();
        unsigned int old = atomicAdd(&g_done, 1u);
        if (old == NBLOCKS - 1u) {
            double t = *((volatile double*)&g_sum);
            float v = (float)(1.0 - t / TOTAL_OUT);
            for (int i2 = 0; i2 < out_n; ++i2) out[i2] = v;
            // reset for next graph replay (deterministic)
            g_sum = 0.0;
            g_done = 0u;
        }
    }
}

extern "C" void kernel_launch(void* const* d_in, const int* in_sizes, int n_in,
                              void* d_out, int out_size) {
    const float* pred   = (const float*)d_in[0];
    const float* target = (const float*)d_in[1];

    constexpr size_t SMEM = (size_t)(4 * IN_TY * TX) * sizeof(float);   // 49152 B
    cudaFuncSetAttribute(ssim_kernel, cudaFuncAttributeMaxDynamicSharedMemorySize, (int)SMEM);

    dim3 grid(TILES_X, TILES_Y, NCH);
    ssim_kernel<<<grid, 256, SMEM>>>(pred, target, (float*)d_out, out_size);
}